// round 17
// baseline (speedup 1.0000x reference)
#include <cuda_runtime.h>

#define FULL 0xFFFFFFFFu
#define IDM  0x7FFFFFFF

// Precomputed v[i,d] = sum_e W_bil[d,e] * item_table[i,e]  (NI=50000, D=32)
__device__ float g_vtab[50000 * 32];
// Mask dtype mode: 0 = int32, 1 = float32, 2 = uint8
__device__ int g_mask_mode;

// bf16x2 pack/reduce helpers: A rides in the HIGH half, B in the LOW half.
__device__ __forceinline__ unsigned packbf(float hi, float lo) {
    unsigned d; asm("cvt.rn.bf16x2.f32 %0,%1,%2;" : "=r"(d) : "f"(hi), "f"(lo)); return d;
}
__device__ __forceinline__ unsigned badd2(unsigned a, unsigned b) {
    unsigned d; asm("add.rn.bf16x2 %0,%1,%2;" : "=r"(d) : "r"(a), "r"(b)); return d;
}
__device__ __forceinline__ float blo(unsigned w) { return __int_as_float((int)(w << 16)); }
__device__ __forceinline__ float bhi(unsigned w) { return __int_as_float((int)(w & 0xFFFF0000u)); }

// ---------------------------------------------------------------------------
// Precompute: v = item_table @ W_bil^T. Thread = (item i, dim-quad q).
// Sniffs mask dtype from word 0 (mask[0,0] true since lengths >= 1).
// ---------------------------------------------------------------------------
__global__ void __launch_bounds__(256) vtab_kernel(
    const float* __restrict__ W_bil,
    const float* __restrict__ item_table,
    const unsigned int* __restrict__ mask_words,
    int NI)
{
    __shared__ float WT[1024];   // WT[e*32 + d] = W_bil[d*32 + e]
    int t = threadIdx.x;

    if (blockIdx.x == 0 && t == 0) {
        unsigned int w0 = mask_words[0];
        int mode;
        if (w0 == 1u)               mode = 0;
        else if (w0 == 0x3F800000u) mode = 1;
        else                        mode = 2;
        g_mask_mode = mode;
    }

    for (int k = t; k < 1024; k += 256) {
        int d = k & 31, e = k >> 5;
        WT[e * 32 + d] = W_bil[d * 32 + e];
    }
    __syncthreads();

    const int idx = blockIdx.x * 256 + t;
    const int i = idx >> 3, q = idx & 7;
    if (i >= NI) return;

    const float4* __restrict__ itr = (const float4*)(item_table + i * 32);
    const float4* __restrict__ wt4 = (const float4*)WT;
    float4 acc = make_float4(0.f, 0.f, 0.f, 0.f);
    #pragma unroll
    for (int eq = 0; eq < 8; eq++) {
        const float4 it4 = itr[eq];
        #pragma unroll
        for (int j = 0; j < 4; j++) {
            const float x = (j == 0) ? it4.x : (j == 1) ? it4.y : (j == 2) ? it4.z : it4.w;
            const float4 w = wt4[(4 * eq + j) * 8 + q];
            acc.x = fmaf(w.x, x, acc.x); acc.y = fmaf(w.y, x, acc.y);
            acc.z = fmaf(w.z, x, acc.z); acc.w = fmaf(w.w, x, acc.w);
        }
    }
    ((float4*)g_vtab)[i * 8 + q] = acc;
}

__device__ __forceinline__ float dot4(const float4 a, const float4 b) {
    return fmaf(a.x, b.x, fmaf(a.y, b.y, fmaf(a.z, b.z, a.w * b.w)));
}

// ---------------------------------------------------------------------------
// Main kernel (R15 structure + bf16x2-PACKED cross-lane reduces).
// One warp, TWO pairs/iter. lane = (g = lane>>3 member group, c = lane&7
// float4 dim-chunk), slot i = member 4i+g (4-line gathers). All dot/fma math
// f32; at every butterfly the (pairA, pairB) values are packed into one
// bf16x2 word -> HALF the SHFL traffic on the l1tex crossbar (the measured
// bottleneck: ~61 shfl/iter = ~100 of 149 l1tex-cyc).
// ---------------------------------------------------------------------------
__global__ void __launch_bounds__(256, 3) bilinear_main_kernel(
    const int*           __restrict__ item_inputs,
    const int*           __restrict__ member_ids,
    const void*          __restrict__ member_mask,
    const float*         __restrict__ user_table,
    const float*         __restrict__ item_table,
    const float*         __restrict__ b_bil,
    const float*         __restrict__ W1,
    const float*         __restrict__ b1,
    const float*         __restrict__ W2,
    const float*         __restrict__ b2,
    float*               __restrict__ out,
    int B)
{
    __shared__ float w1s[768];      // W1 [8][96]
    for (int k = threadIdx.x; k < 768; k += 256) w1s[k] = W1[k];
    __syncthreads();

    const int lane   = threadIdx.x & 31;
    const int warp   = (blockIdx.x * blockDim.x + threadIdx.x) >> 5;
    const int nwarps = (gridDim.x * blockDim.x) >> 5;

    const int g   = lane >> 3;
    const int c   = lane & 7;
    const int rho = (c >> 2) & 1;
    const int j0 = 2 * g + rho;       // owned MLP unit
    const int j1 = 2 * g + (1 ^ rho);

    const float b1c = b1[j0];
    const float w2c = W2[j0];         // orbit tail reduce counts each unit once
    const float bb  = b_bil[0];
    const float b2v = b2[0];
    const int   mmode = g_mask_mode;
    const int   half  = lane >> 4;
    const int   memi  = lane & 15;

    const unsigned w1_0 = (unsigned)__cvta_generic_to_shared(&w1s[j0 * 96 + 4 * c]);
    const unsigned w1_1 = (unsigned)__cvta_generic_to_shared(&w1s[j1 * 96 + 4 * c]);

    const float4* __restrict__ ut4  = (const float4*)user_table;
    const float4* __restrict__ it4p = (const float4*)item_table;
    const float4* __restrict__ vt4p = (const float4*)g_vtab;

    const int step = 2 * nwarps;
    int base = 2 * warp;

    // Prefetch scalar control for the first iteration.
    int pk, itmA, itmB;
    {
        const int bA0 = (base     < B) ? base     : (B - 1);
        const int bB0 = (base + 1 < B) ? base + 1 : (B - 1);
        itmA = item_inputs[bA0];
        itmB = item_inputs[bB0];
        const int bH = half ? bB0 : bA0;
        const int mid = member_ids[bH * 16 + memi];
        int mkbit;
        if (mmode == 0)      mkbit = (((const int*)member_mask)[bH * 16 + memi] != 0);
        else if (mmode == 1) mkbit = (((const float*)member_mask)[bH * 16 + memi] != 0.f);
        else                 mkbit = (((const unsigned char*)member_mask)[bH * 16 + memi] != 0);
        pk = mid | (mkbit << 31);
    }

    for (; base < B; base += step) {
        // ---- gathers off the prefetched scalars ----
        const int pA0 = __shfl_sync(FULL, pk,      0 + g);
        const int pA1 = __shfl_sync(FULL, pk,      4 + g);
        const int pA2 = __shfl_sync(FULL, pk,      8 + g);
        const int pA3 = __shfl_sync(FULL, pk,     12 + g);
        const int pB0 = __shfl_sync(FULL, pk, 16 + 0 + g);
        const int pB1 = __shfl_sync(FULL, pk, 16 + 4 + g);
        const int pB2 = __shfl_sync(FULL, pk, 16 + 8 + g);
        const int pB3 = __shfl_sync(FULL, pk, 16 + 12 + g);

        const float4 mA0 = ut4[(pA0 & IDM) * 8 + c];
        const float4 mA1 = ut4[(pA1 & IDM) * 8 + c];
        const float4 mA2 = ut4[(pA2 & IDM) * 8 + c];
        const float4 mA3 = ut4[(pA3 & IDM) * 8 + c];
        const float4 mB0 = ut4[(pB0 & IDM) * 8 + c];
        const float4 mB1 = ut4[(pB1 & IDM) * 8 + c];
        const float4 mB2 = ut4[(pB2 & IDM) * 8 + c];
        const float4 mB3 = ut4[(pB3 & IDM) * 8 + c];

        const float4 itA = it4p[itmA * 8 + c];
        const float4 vA  = vt4p[itmA * 8 + c];
        const float4 itB = it4p[itmB * 8 + c];
        const float4 vB  = vt4p[itmB * 8 + c];

        const unsigned mbA = ((unsigned)pA0 >> 31)        | (((unsigned)pA1 >> 30) & 2u)
                           | (((unsigned)pA2 >> 29) & 4u) | (((unsigned)pA3 >> 28) & 8u);
        const unsigned mbB = ((unsigned)pB0 >> 31)        | (((unsigned)pB1 >> 30) & 2u)
                           | (((unsigned)pB2 >> 29) & 4u) | (((unsigned)pB3 >> 28) & 8u);

        // ---- prefetch next iteration's scalar control ----
        {
            const int nb  = base + step;
            const int bAn = (nb     < B) ? nb     : (B - 1);
            const int bBn = (nb + 1 < B) ? nb + 1 : (B - 1);
            itmA = item_inputs[bAn];
            itmB = item_inputs[bBn];
            const int bH = half ? bBn : bAn;
            const int mid = member_ids[bH * 16 + memi];
            int mkbit;
            if (mmode == 0)      mkbit = (((const int*)member_mask)[bH * 16 + memi] != 0);
            else if (mmode == 1) mkbit = (((const float*)member_mask)[bH * 16 + memi] != 0.f);
            else                 mkbit = (((const unsigned char*)member_mask)[bH * 16 + memi] != 0);
            pk = mid | (mkbit << 31);
        }

        // ---- score dots (f32) -> PACKED (A|B) bf16x2 butterfly, 12 shfl ----
        unsigned z0 = packbf(dot4(mA0, vA), dot4(mB0, vB));
        unsigned z1 = packbf(dot4(mA1, vA), dot4(mB1, vB));
        unsigned z2 = packbf(dot4(mA2, vA), dot4(mB2, vB));
        unsigned z3 = packbf(dot4(mA3, vA), dot4(mB3, vB));

        z0 = badd2(z0, __shfl_xor_sync(FULL, z0, 4));
        z1 = badd2(z1, __shfl_xor_sync(FULL, z1, 4));
        z2 = badd2(z2, __shfl_xor_sync(FULL, z2, 4));
        z3 = badd2(z3, __shfl_xor_sync(FULL, z3, 4));
        z0 = badd2(z0, __shfl_xor_sync(FULL, z0, 2));
        z1 = badd2(z1, __shfl_xor_sync(FULL, z1, 2));
        z2 = badd2(z2, __shfl_xor_sync(FULL, z2, 2));
        z3 = badd2(z3, __shfl_xor_sync(FULL, z3, 2));
        z0 = badd2(z0, __shfl_xor_sync(FULL, z0, 1));
        z1 = badd2(z1, __shfl_xor_sync(FULL, z1, 1));
        z2 = badd2(z2, __shfl_xor_sync(FULL, z2, 1));
        z3 = badd2(z3, __shfl_xor_sync(FULL, z3, 1));

        // Masked weights (f32), locally on every lane.
        const float wA0 = (mbA & 1u) ? (bhi(z0) + bb) : 0.f;
        const float wA1 = (mbA & 2u) ? (bhi(z1) + bb) : 0.f;
        const float wA2 = (mbA & 4u) ? (bhi(z2) + bb) : 0.f;
        const float wA3 = (mbA & 8u) ? (bhi(z3) + bb) : 0.f;
        const float wB0 = (mbB & 1u) ? (blo(z0) + bb) : 0.f;
        const float wB1 = (mbB & 2u) ? (blo(z1) + bb) : 0.f;
        const float wB2 = (mbB & 4u) ? (blo(z2) + bb) : 0.f;
        const float wB3 = (mbB & 8u) ? (blo(z3) + bb) : 0.f;

        // ---- fu partials (f32 FMA) ----
        float fAx = wA0 * mA0.x, fAy = wA0 * mA0.y, fAz = wA0 * mA0.z, fAw = wA0 * mA0.w;
        fAx = fmaf(wA1, mA1.x, fAx); fAy = fmaf(wA1, mA1.y, fAy);
        fAz = fmaf(wA1, mA1.z, fAz); fAw = fmaf(wA1, mA1.w, fAw);
        fAx = fmaf(wA2, mA2.x, fAx); fAy = fmaf(wA2, mA2.y, fAy);
        fAz = fmaf(wA2, mA2.z, fAz); fAw = fmaf(wA2, mA2.w, fAw);
        fAx = fmaf(wA3, mA3.x, fAx); fAy = fmaf(wA3, mA3.y, fAy);
        fAz = fmaf(wA3, mA3.z, fAz); fAw = fmaf(wA3, mA3.w, fAw);

        float fBx = wB0 * mB0.x, fBy = wB0 * mB0.y, fBz = wB0 * mB0.z, fBw = wB0 * mB0.w;
        fBx = fmaf(wB1, mB1.x, fBx); fBy = fmaf(wB1, mB1.y, fBy);
        fBz = fmaf(wB1, mB1.z, fBz); fBw = fmaf(wB1, mB1.w, fBw);
        fBx = fmaf(wB2, mB2.x, fBx); fBy = fmaf(wB2, mB2.y, fBy);
        fBz = fmaf(wB2, mB2.z, fBz); fBw = fmaf(wB2, mB2.w, fBw);
        fBx = fmaf(wB3, mB3.x, fBx); fBy = fmaf(wB3, mB3.y, fBy);
        fBz = fmaf(wB3, mB3.z, fBz); fBw = fmaf(wB3, mB3.w, fBw);

        // ---- fu reduce over g: PACKED (A|B), 8 shfl (was 16) ----
        unsigned ux = packbf(fAx, fBx), uy = packbf(fAy, fBy);
        unsigned uz = packbf(fAz, fBz), uw = packbf(fAw, fBw);
        ux = badd2(ux, __shfl_xor_sync(FULL, ux, 8));
        uy = badd2(uy, __shfl_xor_sync(FULL, uy, 8));
        uz = badd2(uz, __shfl_xor_sync(FULL, uz, 8));
        uw = badd2(uw, __shfl_xor_sync(FULL, uw, 8));
        ux = badd2(ux, __shfl_xor_sync(FULL, ux, 16));
        uy = badd2(uy, __shfl_xor_sync(FULL, uy, 16));
        uz = badd2(uz, __shfl_xor_sync(FULL, uz, 16));
        uw = badd2(uw, __shfl_xor_sync(FULL, uw, 16));
        const float FAx = bhi(ux), FAy = bhi(uy), FAz = bhi(uz), FAw = bhi(uw);
        const float FBx = blo(ux), FBy = blo(uy), FBz = blo(uz), FBw = blo(uw);

        // ---- MLP layer 1 (f32). ne = fu*it ----
        const float nAx = FAx * itA.x, nAy = FAy * itA.y;
        const float nAz = FAz * itA.z, nAw = FAw * itA.w;
        const float nBx = FBx * itB.x, nBy = FBy * itB.y;
        const float nBz = FBz * itB.z, nBw = FBw * itB.w;

        float a00,a01,a02,a03, b00,b01,b02,b03, c00,c01,c02,c03;
        float a10,a11,a12,a13, b10,b11,b12,b13, c10,c11,c12,c13;
        asm volatile("ld.shared.v4.f32 {%0,%1,%2,%3},[%4];"
            : "=f"(a00),"=f"(a01),"=f"(a02),"=f"(a03) : "r"(w1_0));
        asm volatile("ld.shared.v4.f32 {%0,%1,%2,%3},[%4];"
            : "=f"(b00),"=f"(b01),"=f"(b02),"=f"(b03) : "r"(w1_0 + 128));
        asm volatile("ld.shared.v4.f32 {%0,%1,%2,%3},[%4];"
            : "=f"(c00),"=f"(c01),"=f"(c02),"=f"(c03) : "r"(w1_0 + 256));
        asm volatile("ld.shared.v4.f32 {%0,%1,%2,%3},[%4];"
            : "=f"(a10),"=f"(a11),"=f"(a12),"=f"(a13) : "r"(w1_1));
        asm volatile("ld.shared.v4.f32 {%0,%1,%2,%3},[%4];"
            : "=f"(b10),"=f"(b11),"=f"(b12),"=f"(b13) : "r"(w1_1 + 128));
        asm volatile("ld.shared.v4.f32 {%0,%1,%2,%3},[%4];"
            : "=f"(c10),"=f"(c11),"=f"(c12),"=f"(c13) : "r"(w1_1 + 256));

        float PA0, PA1, PB0, PB1;
        {
            float t;
            t = a00 * nAx; t = fmaf(b00, FAx, t); t = fmaf(c00, itA.x, t);
            t = fmaf(a01, nAy, t); t = fmaf(b01, FAy, t); t = fmaf(c01, itA.y, t);
            t = fmaf(a02, nAz, t); t = fmaf(b02, FAz, t); t = fmaf(c02, itA.z, t);
            t = fmaf(a03, nAw, t); t = fmaf(b03, FAw, t); t = fmaf(c03, itA.w, t);
            PA0 = t;
            t = a10 * nAx; t = fmaf(b10, FAx, t); t = fmaf(c10, itA.x, t);
            t = fmaf(a11, nAy, t); t = fmaf(b11, FAy, t); t = fmaf(c11, itA.y, t);
            t = fmaf(a12, nAz, t); t = fmaf(b12, FAz, t); t = fmaf(c12, itA.z, t);
            t = fmaf(a13, nAw, t); t = fmaf(b13, FAw, t); t = fmaf(c13, itA.w, t);
            PA1 = t;
            t = a00 * nBx; t = fmaf(b00, FBx, t); t = fmaf(c00, itB.x, t);
            t = fmaf(a01, nBy, t); t = fmaf(b01, FBy, t); t = fmaf(c01, itB.y, t);
            t = fmaf(a02, nBz, t); t = fmaf(b02, FBz, t); t = fmaf(c02, itB.z, t);
            t = fmaf(a03, nBw, t); t = fmaf(b03, FBw, t); t = fmaf(c03, itB.w, t);
            PB0 = t;
            t = a10 * nBx; t = fmaf(b10, FBx, t); t = fmaf(c10, itB.x, t);
            t = fmaf(a11, nBy, t); t = fmaf(b11, FBy, t); t = fmaf(c11, itB.y, t);
            t = fmaf(a12, nBz, t); t = fmaf(b12, FBz, t); t = fmaf(c12, itB.z, t);
            t = fmaf(a13, nBw, t); t = fmaf(b13, FBw, t); t = fmaf(c13, itB.w, t);
            PB1 = t;
        }

        // ---- MLP reduce: PACKED (A|B), select-free (rho perm), 3 shfl ----
        unsigned u0 = packbf(PA0, PB0);
        unsigned u1 = packbf(PA1, PB1);
        unsigned u = badd2(u0, __shfl_xor_sync(FULL, u1, 4));
        u = badd2(u, __shfl_xor_sync(FULL, u, 2));
        u = badd2(u, __shfl_xor_sync(FULL, u, 1));
        const float hA = bhi(u);
        const float hB = blo(u);

        // ---- output layer: PACKED orbit reduce over bits {4,8,16} (each of
        // the 8 units counted exactly once per lane's orbit), 3 shfl ----
        const float tA = w2c * fmaxf(hA + b1c, 0.f);
        const float tB = w2c * fmaxf(hB + b1c, 0.f);
        unsigned zt = packbf(tA, tB);
        zt = badd2(zt, __shfl_xor_sync(FULL, zt, 4));
        zt = badd2(zt, __shfl_xor_sync(FULL, zt, 8));
        zt = badd2(zt, __shfl_xor_sync(FULL, zt, 16));

        const float yA = 1.f / (1.f + __expf(-(bhi(zt) + b2v)));
        const float yB = 1.f / (1.f + __expf(-(blo(zt) + b2v)));
        if (lane == 0) {
            if (base + 1 < B) {
                *(float2*)(out + base) = make_float2(yA, yB);
            } else {
                out[base] = yA;
            }
        }
    }
}

// ---------------------------------------------------------------------------
extern "C" void kernel_launch(void* const* d_in, const int* in_sizes, int n_in,
                              void* d_out, int out_size)
{
    const int*   item_inputs = (const int*)  d_in[0];
    const int*   member_ids  = (const int*)  d_in[1];
    const void*  member_mask =               d_in[2];
    const float* user_table  = (const float*)d_in[3];
    const float* item_table  = (const float*)d_in[4];
    const float* W_bil       = (const float*)d_in[5];
    const float* b_bil       = (const float*)d_in[6];
    const float* W1          = (const float*)d_in[7];
    const float* b1          = (const float*)d_in[8];
    const float* W2          = (const float*)d_in[9];
    const float* b2          = (const float*)d_in[10];
    float* out = (float*)d_out;

    const int B  = in_sizes[0];
    int NI = in_sizes[4] / 32;
    if (NI > 50000) NI = 50000;   // g_vtab capacity (problem spec: NI = 50000)

    vtab_kernel<<<(NI * 8 + 255) / 256, 256>>>(W_bil, item_table,
                                               (const unsigned int*)member_mask, NI);
    bilinear_main_kernel<<<444, 256>>>(item_inputs, member_ids, member_mask,
                                       user_table, item_table,
                                       b_bil, W1, b1, W2, b2, out, B);
}